// round 14
// baseline (speedup 1.0000x reference)
#include <cuda_runtime.h>
#include <cuda_bf16.h>
#include <cstdint>

// Problem constants
#define B_  64
#define S_  2048
#define E_  256
#define H_  256
#define M_TOT (B_ * S_)        // 131072 rows

// Scratch (device-global: runtime allocation is forbidden)
__device__ float         g_xw [(size_t)M_TOT * H_];   // 128 MB
__device__ __nv_bfloat16 g_xhi[(size_t)M_TOT * E_];   // 64 MB
__device__ __nv_bfloat16 g_xlo[(size_t)M_TOT * E_];   // 64 MB
__device__ __nv_bfloat16 g_Whi[H_ * E_];
__device__ __nv_bfloat16 g_Wlo[H_ * E_];
__device__ float         g_UwT[H_ * H_];              // UwT[k][h] = Uw[h][k]

// Fast tanh: 1 - 2/(e^{2x}+1). |err| ~1e-6; exact saturation at +/-inf.
__device__ __forceinline__ float fast_tanh(float x) {
    float e = __expf(2.0f * x);
    float r;
    asm("rcp.approx.f32 %0, %1;" : "=f"(r) : "f"(e + 1.0f));
    return fmaf(-2.0f, r, 1.0f);
}

__device__ __forceinline__ uint32_t smem_u32(const void* p) {
    uint32_t a;
    asm("{ .reg .u64 t; cvta.to.shared.u64 t, %1; cvt.u32.u64 %0, t; }"
        : "=r"(a) : "l"(p));
    return a;
}
__device__ __forceinline__ uint32_t mapa_u32(uint32_t local, uint32_t rank) {
    uint32_t r;
    asm("mapa.shared::cluster.u32 %0, %1, %2;" : "=r"(r) : "r"(local), "r"(rank));
    return r;
}

// ---------------------------------------------------------------------------
// prep kernels
// ---------------------------------------------------------------------------
__global__ void prep_uwt(const float* __restrict__ Uw) {
    int k = blockIdx.x, h = threadIdx.x;
    g_UwT[k * H_ + h] = Uw[h * H_ + k];
}

__global__ void prep_wsplit(const float* __restrict__ Ww) {
    int i = blockIdx.x * 256 + threadIdx.x;
    float v = Ww[i];
    __nv_bfloat16 hb = __float2bfloat16_rn(v);
    g_Whi[i] = hb;
    g_Wlo[i] = __float2bfloat16_rn(v - __bfloat162float(hb));
}

__global__ void prep_xsplit(const float* __restrict__ x) {
    size_t i4 = (size_t)blockIdx.x * blockDim.x + threadIdx.x;
    const size_t n4 = (size_t)M_TOT * E_ / 4;
    for (; i4 < n4; i4 += (size_t)gridDim.x * blockDim.x) {
        float4 v = ((const float4*)x)[i4];
        __nv_bfloat16 h0 = __float2bfloat16_rn(v.x);
        __nv_bfloat16 h1 = __float2bfloat16_rn(v.y);
        __nv_bfloat16 h2 = __float2bfloat16_rn(v.z);
        __nv_bfloat16 h3 = __float2bfloat16_rn(v.w);
        __nv_bfloat16 l0 = __float2bfloat16_rn(v.x - __bfloat162float(h0));
        __nv_bfloat16 l1 = __float2bfloat16_rn(v.y - __bfloat162float(h1));
        __nv_bfloat16 l2 = __float2bfloat16_rn(v.z - __bfloat162float(h2));
        __nv_bfloat16 l3 = __float2bfloat16_rn(v.w - __bfloat162float(h3));
        __nv_bfloat162* ph = (__nv_bfloat162*)&g_xhi[i4 * 4];
        __nv_bfloat162* pl = (__nv_bfloat162*)&g_xlo[i4 * 4];
        ph[0] = __nv_bfloat162(h0, h1); ph[1] = __nv_bfloat162(h2, h3);
        pl[0] = __nv_bfloat162(l0, l1); pl[1] = __nv_bfloat162(l2, l3);
    }
}

// ---------------------------------------------------------------------------
// Tensor-core GEMM (unchanged from R13): xw = x_hi*W_hi + x_lo*W_hi + x_hi*W_lo + Wb
// ---------------------------------------------------------------------------
#define ASTRIDE 40
#define BSTRIDE 40

__device__ __forceinline__ void ldmx4(uint32_t& r0, uint32_t& r1, uint32_t& r2, uint32_t& r3,
                                      uint32_t addr) {
    asm volatile("ldmatrix.sync.aligned.m8n8.x4.shared.b16 {%0,%1,%2,%3}, [%4];"
                 : "=r"(r0), "=r"(r1), "=r"(r2), "=r"(r3) : "r"(addr));
}
__device__ __forceinline__ void mma16816(float& d0, float& d1, float& d2, float& d3,
                                         uint32_t a0, uint32_t a1, uint32_t a2, uint32_t a3,
                                         uint32_t b0, uint32_t b1) {
    asm volatile("mma.sync.aligned.m16n8k16.row.col.f32.bf16.bf16.f32 "
                 "{%0,%1,%2,%3}, {%4,%5,%6,%7}, {%8,%9}, {%0,%1,%2,%3};"
                 : "+f"(d0), "+f"(d1), "+f"(d2), "+f"(d3)
                 : "r"(a0), "r"(a1), "r"(a2), "r"(a3), "r"(b0), "r"(b1));
}

__global__ __launch_bounds__(256) void gemm_bf16(const float* __restrict__ Wb) {
    __shared__ __nv_bfloat16 As[128 * ASTRIDE];
    __shared__ __nv_bfloat16 Bs[64 * BSTRIDE];

    const int tid   = threadIdx.x;
    const int lane  = tid & 31;
    const int warp  = tid >> 5;
    const int warpM = warp >> 1;
    const int warpN = warp & 1;
    const int grp   = lane >> 2;
    const int qid   = lane & 3;

    const size_t row0 = (size_t)blockIdx.y * 128;
    const int    n0   = blockIdx.x * 64;

    const int arow = tid >> 1, acol = (tid & 1) * 16;
    const int brow = tid >> 1, bcol = (tid & 1) * 16;

    float d[2][4][4];
    #pragma unroll
    for (int i = 0; i < 2; i++)
        #pragma unroll
        for (int j = 0; j < 4; j++)
            #pragma unroll
            for (int c = 0; c < 4; c++) d[i][j][c] = 0.0f;

    uint32_t as_base = (uint32_t)__cvta_generic_to_shared(As);
    uint32_t bs_base = (uint32_t)__cvta_generic_to_shared(Bs);

    uint4 ra0 = *(const uint4*)&g_xhi[(row0 + arow) * E_ + acol + 0];
    uint4 ra1 = *(const uint4*)&g_xhi[(row0 + arow) * E_ + acol + 8];
    uint4 rb0 = make_uint4(0, 0, 0, 0), rb1 = make_uint4(0, 0, 0, 0);
    if (tid < 128) {
        rb0 = *(const uint4*)&g_Whi[(size_t)(n0 + brow) * E_ + bcol + 0];
        rb1 = *(const uint4*)&g_Whi[(size_t)(n0 + brow) * E_ + bcol + 8];
    }

    for (int it = 0; it < 24; it++) {
        *(uint4*)&As[arow * ASTRIDE + acol + 0] = ra0;
        *(uint4*)&As[arow * ASTRIDE + acol + 8] = ra1;
        if (tid < 128) {
            *(uint4*)&Bs[brow * BSTRIDE + bcol + 0] = rb0;
            *(uint4*)&Bs[brow * BSTRIDE + bcol + 8] = rb1;
        }
        __syncthreads();

        if (it + 1 < 24) {
            int nit = it + 1;
            int seg = nit >> 3, kc = nit & 7;
            const __nv_bfloat16* nA = (seg == 1) ? g_xlo : g_xhi;
            const __nv_bfloat16* nB = (seg == 2) ? g_Wlo : g_Whi;
            ra0 = *(const uint4*)&nA[(row0 + arow) * E_ + kc * 32 + acol + 0];
            ra1 = *(const uint4*)&nA[(row0 + arow) * E_ + kc * 32 + acol + 8];
            if (tid < 128) {
                rb0 = *(const uint4*)&nB[(size_t)(n0 + brow) * E_ + kc * 32 + bcol + 0];
                rb1 = *(const uint4*)&nB[(size_t)(n0 + brow) * E_ + kc * 32 + bcol + 8];
            }
        }

        #pragma unroll
        for (int k16 = 0; k16 < 32; k16 += 16) {
            uint32_t a[2][4], b[2][4];
            #pragma unroll
            for (int i = 0; i < 2; i++) {
                int r = warpM * 32 + i * 16 + (lane & 15);
                int c = k16 + ((lane >> 4) << 3);
                ldmx4(a[i][0], a[i][1], a[i][2], a[i][3],
                      as_base + (uint32_t)(r * ASTRIDE + c) * 2);
            }
            #pragma unroll
            for (int j2 = 0; j2 < 2; j2++) {
                int n = warpN * 32 + j2 * 16 + (((lane >> 4) & 1) << 3) + (lane & 7);
                int c = k16 + (((lane >> 3) & 1) << 3);
                ldmx4(b[j2][0], b[j2][1], b[j2][2], b[j2][3],
                      bs_base + (uint32_t)(n * BSTRIDE + c) * 2);
            }
            #pragma unroll
            for (int i = 0; i < 2; i++)
                #pragma unroll
                for (int j = 0; j < 4; j++) {
                    int j2 = j >> 1, sel = (j & 1) * 2;
                    mma16816(d[i][j][0], d[i][j][1], d[i][j][2], d[i][j][3],
                             a[i][0], a[i][1], a[i][2], a[i][3],
                             b[j2][sel], b[j2][sel + 1]);
                }
        }
        __syncthreads();
    }

    #pragma unroll
    for (int j = 0; j < 4; j++) {
        int col = n0 + warpN * 32 + j * 8 + qid * 2;
        float2 wb = *(const float2*)&Wb[col];
        #pragma unroll
        for (int i = 0; i < 2; i++) {
            size_t r = row0 + warpM * 32 + i * 16 + grp;
            float2 o0 = make_float2(d[i][j][0] + wb.x, d[i][j][1] + wb.y);
            float2 o1 = make_float2(d[i][j][2] + wb.x, d[i][j][3] + wb.y);
            *(float2*)&g_xw[r * H_ + col]       = o0;
            *(float2*)&g_xw[(r + 8) * H_ + col] = o1;
        }
    }
}

// ---------------------------------------------------------------------------
// Scan: 2-CTA cluster per batch, 128 threads/CTA. CTA r owns h in
// [128r, 128r+128). Per step: own v-half -> local smem + peer smem (DSMEM),
// release-arrive on peer mbar, dot own-k half (no wait), acquire-wait,
// dot peer-k half.  Per-SM FMA floor: 512 cyc (half of single-CTA scan).
// ---------------------------------------------------------------------------
#define CB 128                 // threads per CTA / h per CTA
#define PREGS 64               // peer-half k rows in registers
#define PSMEM (CB - PREGS)     // 64 peer-half k rows in smem (32 float2 pairs)

__global__ void __launch_bounds__(CB, 1) __cluster_dims__(2, 1, 1)
rnn_scan2(const float* __restrict__ Ub,
          float* __restrict__ Out,     // [B,S,H]
          float* __restrict__ Tfin) {  // [B,H]
    __shared__ float2 u2s[(PSMEM / 2) * CB];     // 32 pair-rows x 128 h = 32 KB
    __shared__ float  vbuf[2][H_];               // full v, double-buffered
    __shared__ __align__(8) unsigned long long mbar;

    const int tid   = threadIdx.x;
    const int rank  = blockIdx.x & 1;            // cluster rank
    const int peer  = rank ^ 1;
    const int b     = blockIdx.x >> 1;
    const int h     = rank * CB + tid;           // owned global h
    const int ownk0 = rank * CB;                 // own-half k base
    const int prk0  = peer * CB;                 // peer-half k base

    // uw_own[j] = Uw[h][ownk0+j], j=0..127 (registers)
    float uw_own[CB];
    #pragma unroll
    for (int j = 0; j < CB; j++)
        uw_own[j] = g_UwT[(ownk0 + j) * H_ + h];

    // peer-half: first PREGS in registers, rest in smem float2 pairs
    float uw_peer[PREGS];
    #pragma unroll
    for (int j = 0; j < PREGS; j++)
        uw_peer[j] = g_UwT[(prk0 + j) * H_ + h];
    for (int r2 = 0; r2 < PSMEM / 2; r2++) {
        float a = g_UwT[(prk0 + PREGS + 2 * r2 + 0) * H_ + h];
        float c = g_UwT[(prk0 + PREGS + 2 * r2 + 1) * H_ + h];
        u2s[r2 * CB + tid] = make_float2(a, c);
    }

    if (tid == 0) {
        uint32_t mb = smem_u32(&mbar);
        asm volatile("mbarrier.init.shared.b64 [%0], %1;" :: "r"(mb), "r"(CB) : "memory");
    }
    __syncthreads();
    // cluster barrier: peer's mbar must be initialized before any remote arrive
    asm volatile("barrier.cluster.arrive.aligned;" ::: "memory");
    asm volatile("barrier.cluster.wait.aligned;" ::: "memory");

    const uint32_t mb_local = smem_u32(&mbar);
    const uint32_t mb_peer  = mapa_u32(mb_local, (uint32_t)peer);

    const float ub = Ub[h];
    float t = 0.0f;

    const float* xwp = g_xw + (size_t)b * S_ * H_ + h;
    float*       op  = Out  + (size_t)b * S_ * H_ + h;

    float xv = __ldcs(xwp);
    float xn = __ldcs(xwp + H_);    // prefetch step 1

    for (int s = 0; s < S_; s++) {
        const int p = s & 1;
        float v = fast_tanh(xv + t);

        // own v -> local smem and peer smem (same offset, DSMEM)
        vbuf[p][h] = v;
        {
            uint32_t la = smem_u32(&vbuf[p][h]);
            uint32_t pa = mapa_u32(la, (uint32_t)peer);
            asm volatile("st.shared::cluster.f32 [%0], %1;" :: "r"(pa), "f"(v) : "memory");
        }
        // release-arrive on peer's barrier (orders this thread's remote store);
        // MUST precede bar.sync so all phase-s arrivals land before any s+1.
        asm volatile("mbarrier.arrive.release.cluster.shared::cluster.b64 _, [%0];"
                     :: "r"(mb_peer) : "memory");
        __syncthreads();                          // local half complete

        // prefetch xw for step s+2 (always valid; GEMM finished)
        float xf = (s + 2 < S_) ? __ldcs(xwp + (size_t)(s + 2) * H_) : 0.0f;

        float a0 = ub, a1 = 0.f, a2 = 0.f, a3 = 0.f;

        // ---- own-half dot: k in [ownk0, ownk0+128), v local-fresh ----
        {
            const float4* vq = (const float4*)&vbuf[p][ownk0];
            float4 vA = vq[0];
            #pragma unroll
            for (int q = 0; q < 32; q++) {
                float4 nA;
                if (q + 1 < 32) nA = vq[q + 1];
                const int j = 4 * q;
                a0 += uw_own[j + 0] * vA.x;
                a1 += uw_own[j + 1] * vA.y;
                a2 += uw_own[j + 2] * vA.z;
                a3 += uw_own[j + 3] * vA.w;
                vA = nA;
            }
        }

        // ---- wait for peer half (acquire, cluster scope) ----
        {
            uint32_t done;
            asm volatile(
                "{\n\t.reg .pred P;\n\t"
                "mbarrier.try_wait.parity.acquire.cluster.shared::cta.b64 P, [%1], %2;\n\t"
                "selp.b32 %0, 1, 0, P;\n\t}"
                : "=r"(done) : "r"(mb_local), "r"((uint32_t)p) : "memory");
            if (!done) {
                asm volatile(
                    "{\n\t.reg .pred P;\n\t"
                    "WL_%=:\n\t"
                    "mbarrier.try_wait.parity.acquire.cluster.shared::cta.b64 P, [%0], %1;\n\t"
                    "@P bra.uni WD_%=;\n\t"
                    "bra.uni WL_%=;\n\t"
                    "WD_%=:\n\t}"
                    :: "r"(mb_local), "r"((uint32_t)p) : "memory");
            }
        }

        // ---- peer-half dot: k in [prk0, prk0+128) ----
        {
            const float4* vq = (const float4*)&vbuf[p][prk0];
            float4 vA = vq[0];
            // register part: 16 quads
            #pragma unroll
            for (int q = 0; q < PREGS / 4; q++) {
                float4 nA = vq[q + 1];
                const int j = 4 * q;
                a0 += uw_peer[j + 0] * vA.x;
                a1 += uw_peer[j + 1] * vA.y;
                a2 += uw_peer[j + 2] * vA.z;
                a3 += uw_peer[j + 3] * vA.w;
                vA = nA;
            }
            // smem part: 16 quads via float2 pair rows
            const float2* up = u2s + tid;
            #pragma unroll
            for (int q = PREGS / 4; q < 32; q += 2) {
                float4 vB = vq[q + 1];
                float4 nA;
                if (q + 2 < 32) nA = vq[q + 2];
                const int r2b = (4 * q - PREGS) >> 1;
                float2 u0 = up[(r2b + 0) * CB];
                float2 u1 = up[(r2b + 1) * CB];
                float2 u2v = up[(r2b + 2) * CB];
                float2 u3 = up[(r2b + 3) * CB];
                a0 += u0.x * vA.x;   a1 += u0.y * vA.y;
                a2 += u1.x * vA.z;   a3 += u1.y * vA.w;
                a0 += u2v.x * vB.x;  a1 += u2v.y * vB.y;
                a2 += u3.x * vB.z;   a3 += u3.y * vB.w;
                vA = nA;
            }
        }

        t = (a0 + a1) + (a2 + a3);
        __stcs(&op[(size_t)s * H_], t);

        xv = xn;
        xn = xf;
    }

    Tfin[b * H_ + h] = t;

    // no CTA may exit while peer remote ops could be in flight
    asm volatile("barrier.cluster.arrive.aligned;" ::: "memory");
    asm volatile("barrier.cluster.wait.aligned;" ::: "memory");
}

// ---------------------------------------------------------------------------
// Launcher (serial: prep -> tensor-core GEMM -> clustered scan)
// ---------------------------------------------------------------------------
extern "C" void kernel_launch(void* const* d_in, const int* in_sizes, int n_in,
                              void* d_out, int out_size) {
    const float* x  = (const float*)d_in[0];   // [B,S,E]
    const float* Ww = (const float*)d_in[1];   // [H,E]
    const float* Wb = (const float*)d_in[2];   // [H]
    const float* Uw = (const float*)d_in[3];   // [H,H]
    const float* Ub = (const float*)d_in[4];   // [H]

    float* out  = (float*)d_out;
    float* tfin = out;                          // [B,H]
    float* O    = out + (size_t)B_ * H_;        // [B,S,H]

    prep_uwt<<<H_, H_>>>(Uw);
    prep_wsplit<<<H_, H_>>>(Ww);
    prep_xsplit<<<2048, 256>>>(x);
    gemm_bf16<<<dim3(H_ / 64, M_TOT / 128), 256>>>(Wb);
    rnn_scan2<<<2 * B_, CB>>>(Ub, O, tfin);     // cluster dims from attribute
}

// round 15
// speedup vs baseline: 1.1542x; 1.1542x over previous
#include <cuda_runtime.h>
#include <cuda_bf16.h>
#include <cstdint>

// Problem constants
#define B_  64
#define S_  2048
#define E_  256
#define H_  256
#define M_TOT (B_ * S_)        // 131072 rows

// Scratch (device-global: runtime allocation is forbidden)
__device__ float         g_xw [(size_t)M_TOT * H_];   // 128 MB
__device__ __nv_bfloat16 g_Whi[H_ * E_];
__device__ __nv_bfloat16 g_Wlo[H_ * E_];
__device__ float         g_UwT[H_ * H_];              // UwT[k][h] = Uw[h][k]

// Fast tanh: 1 - 2/(e^{2x}+1). |err| ~1e-6; exact saturation at +/-inf.
__device__ __forceinline__ float fast_tanh(float x) {
    float e = __expf(2.0f * x);
    float r;
    asm("rcp.approx.f32 %0, %1;" : "=f"(r) : "f"(e + 1.0f));
    return fmaf(-2.0f, r, 1.0f);
}

// ---------------------------------------------------------------------------
// prep kernels (tiny)
// ---------------------------------------------------------------------------
__global__ void prep_uwt(const float* __restrict__ Uw) {
    int k = blockIdx.x, h = threadIdx.x;
    g_UwT[k * H_ + h] = Uw[h * H_ + k];
}

__global__ void prep_wsplit(const float* __restrict__ Ww) {
    int i = blockIdx.x * 256 + threadIdx.x;
    float v = Ww[i];
    __nv_bfloat16 hb = __float2bfloat16_rn(v);
    g_Whi[i] = hb;
    g_Wlo[i] = __float2bfloat16_rn(v - __bfloat162float(hb));
}

// ---------------------------------------------------------------------------
// Fused split-bf16 tensor-core GEMM:
//   xw = x_hi*W_hi + x_lo*W_hi + x_hi*W_lo + Wb
//   x loaded fp32, split in-register (no prep pass, no xhi/xlo gmem traffic).
//   CTA tile 128(M) x 128(N), 8 warps = 4(M) x 2(N), warp tile 32 x 64.
//   K chunks of 32; hi+lo tiles resident -> 3 mma products per fragment pair.
//   smem stride 40 bf16 (80B) -> conflict-free ldmatrix. 40 KB static smem.
// ---------------------------------------------------------------------------
#define ASTR 40
#define CTM 128
#define CTN 128

__device__ __forceinline__ void ldmx4(uint32_t& r0, uint32_t& r1, uint32_t& r2, uint32_t& r3,
                                      uint32_t addr) {
    asm volatile("ldmatrix.sync.aligned.m8n8.x4.shared.b16 {%0,%1,%2,%3}, [%4];"
                 : "=r"(r0), "=r"(r1), "=r"(r2), "=r"(r3) : "r"(addr));
}
__device__ __forceinline__ void mma16816(float* d,
                                         const uint32_t* a,
                                         uint32_t b0, uint32_t b1) {
    asm volatile("mma.sync.aligned.m16n8k16.row.col.f32.bf16.bf16.f32 "
                 "{%0,%1,%2,%3}, {%4,%5,%6,%7}, {%8,%9}, {%0,%1,%2,%3};"
                 : "+f"(d[0]), "+f"(d[1]), "+f"(d[2]), "+f"(d[3])
                 : "r"(a[0]), "r"(a[1]), "r"(a[2]), "r"(a[3]), "r"(b0), "r"(b1));
}

// pack 4 fp32 -> (2x bf162 hi, 2x bf162 lo)
__device__ __forceinline__ void split4(float4 v, uint32_t* hi, uint32_t* lo) {
    __nv_bfloat16 h0 = __float2bfloat16_rn(v.x);
    __nv_bfloat16 h1 = __float2bfloat16_rn(v.y);
    __nv_bfloat16 h2 = __float2bfloat16_rn(v.z);
    __nv_bfloat16 h3 = __float2bfloat16_rn(v.w);
    __nv_bfloat162 H0(h0, h1), H1(h2, h3);
    __nv_bfloat162 L0(__float2bfloat16_rn(v.x - __bfloat162float(h0)),
                      __float2bfloat16_rn(v.y - __bfloat162float(h1)));
    __nv_bfloat162 L1(__float2bfloat16_rn(v.z - __bfloat162float(h2)),
                      __float2bfloat16_rn(v.w - __bfloat162float(h3)));
    hi[0] = *(uint32_t*)&H0; hi[1] = *(uint32_t*)&H1;
    lo[0] = *(uint32_t*)&L0; lo[1] = *(uint32_t*)&L1;
}

__global__ __launch_bounds__(256) void gemm_fused(const float* __restrict__ x,
                                                  const float* __restrict__ Wb) {
    __shared__ __nv_bfloat16 Ahi[CTM * ASTR];
    __shared__ __nv_bfloat16 Alo[CTM * ASTR];
    __shared__ __nv_bfloat16 Bhi[CTN * ASTR];
    __shared__ __nv_bfloat16 Blo[CTN * ASTR];

    const int tid   = threadIdx.x;
    const int lane  = tid & 31;
    const int warp  = tid >> 5;
    const int warpM = warp >> 1;           // 0..3, 32 rows each
    const int warpN = warp & 1;            // 0..1, 64 cols each
    const int grp   = lane >> 2;
    const int qid   = lane & 3;

    const size_t row0 = (size_t)blockIdx.y * CTM;
    const int    n0   = blockIdx.x * CTN;

    // Loader coords: 2 threads per row, 16 elements each
    const int arow = tid >> 1, ahalf = (tid & 1) * 16;

    float d[2][8][4];
    #pragma unroll
    for (int i = 0; i < 2; i++)
        #pragma unroll
        for (int j = 0; j < 8; j++)
            #pragma unroll
            for (int c = 0; c < 4; c++) d[i][j][c] = 0.0f;

    uint32_t ah_base = (uint32_t)__cvta_generic_to_shared(Ahi);
    uint32_t al_base = (uint32_t)__cvta_generic_to_shared(Alo);
    uint32_t bh_base = (uint32_t)__cvta_generic_to_shared(Bhi);
    uint32_t bl_base = (uint32_t)__cvta_generic_to_shared(Blo);

    // prefetch chunk 0
    const float* xrow = x + (row0 + arow) * E_ + ahalf;
    const __nv_bfloat16* whrow = g_Whi + (size_t)(n0 + arow) * E_ + ahalf;
    const __nv_bfloat16* wlrow = g_Wlo + (size_t)(n0 + arow) * E_ + ahalf;

    float4 fa0 = *(const float4*)&xrow[0];
    float4 fa1 = *(const float4*)&xrow[4];
    float4 fa2 = *(const float4*)&xrow[8];
    float4 fa3 = *(const float4*)&xrow[12];
    uint4 wh0 = *(const uint4*)&whrow[0];
    uint4 wh1 = *(const uint4*)&whrow[8];
    uint4 wl0 = *(const uint4*)&wlrow[0];
    uint4 wl1 = *(const uint4*)&wlrow[8];

    for (int kc = 0; kc < 8; kc++) {
        // split A in-register, store hi/lo + B hi/lo to smem
        {
            uint32_t h[8], l[8];
            split4(fa0, h + 0, l + 0);
            split4(fa1, h + 2, l + 2);
            split4(fa2, h + 4, l + 4);
            split4(fa3, h + 6, l + 6);
            *(uint4*)&Ahi[arow * ASTR + ahalf + 0] = make_uint4(h[0], h[1], h[2], h[3]);
            *(uint4*)&Ahi[arow * ASTR + ahalf + 8] = make_uint4(h[4], h[5], h[6], h[7]);
            *(uint4*)&Alo[arow * ASTR + ahalf + 0] = make_uint4(l[0], l[1], l[2], l[3]);
            *(uint4*)&Alo[arow * ASTR + ahalf + 8] = make_uint4(l[4], l[5], l[6], l[7]);
            *(uint4*)&Bhi[arow * ASTR + ahalf + 0] = wh0;
            *(uint4*)&Bhi[arow * ASTR + ahalf + 8] = wh1;
            *(uint4*)&Blo[arow * ASTR + ahalf + 0] = wl0;
            *(uint4*)&Blo[arow * ASTR + ahalf + 8] = wl1;
        }
        __syncthreads();

        // prefetch next chunk
        if (kc + 1 < 8) {
            const int ko = (kc + 1) * 32;
            fa0 = *(const float4*)&xrow[ko + 0];
            fa1 = *(const float4*)&xrow[ko + 4];
            fa2 = *(const float4*)&xrow[ko + 8];
            fa3 = *(const float4*)&xrow[ko + 12];
            wh0 = *(const uint4*)&whrow[ko + 0];
            wh1 = *(const uint4*)&whrow[ko + 8];
            wl0 = *(const uint4*)&wlrow[ko + 0];
            wl1 = *(const uint4*)&wlrow[ko + 8];
        }

        // compute: 2 k16 slices, 3 products each
        #pragma unroll
        for (int k16 = 0; k16 < 32; k16 += 16) {
            uint32_t ahi[2][4], alo[2][4];
            #pragma unroll
            for (int i = 0; i < 2; i++) {
                int r = warpM * 32 + i * 16 + (lane & 15);
                int c = k16 + ((lane >> 4) << 3);
                uint32_t off = (uint32_t)(r * ASTR + c) * 2;
                ldmx4(ahi[i][0], ahi[i][1], ahi[i][2], ahi[i][3], ah_base + off);
                ldmx4(alo[i][0], alo[i][1], alo[i][2], alo[i][3], al_base + off);
            }
            #pragma unroll
            for (int j2 = 0; j2 < 4; j2++) {
                int n = warpN * 64 + j2 * 16 + (((lane >> 4) & 1) << 3) + (lane & 7);
                int c = k16 + (((lane >> 3) & 1) << 3);
                uint32_t off = (uint32_t)(n * ASTR + c) * 2;
                uint32_t bh[4], bl[4];
                ldmx4(bh[0], bh[1], bh[2], bh[3], bh_base + off);
                ldmx4(bl[0], bl[1], bl[2], bl[3], bl_base + off);
                #pragma unroll
                for (int i = 0; i < 2; i++)
                    #pragma unroll
                    for (int sel = 0; sel < 2; sel++) {
                        float* dd = d[i][j2 * 2 + sel];
                        mma16816(dd, ahi[i], bh[sel * 2], bh[sel * 2 + 1]);  // hi*hi
                        mma16816(dd, alo[i], bh[sel * 2], bh[sel * 2 + 1]);  // lo*hi
                        mma16816(dd, ahi[i], bl[sel * 2], bl[sel * 2 + 1]);  // hi*lo
                    }
            }
        }
        __syncthreads();
    }

    // epilogue: add bias, store fp32
    #pragma unroll
    for (int j = 0; j < 8; j++) {
        int col = n0 + warpN * 64 + j * 8 + qid * 2;
        float2 wb = *(const float2*)&Wb[col];
        #pragma unroll
        for (int i = 0; i < 2; i++) {
            size_t r = row0 + warpM * 32 + i * 16 + grp;
            float2 o0 = make_float2(d[i][j][0] + wb.x, d[i][j][1] + wb.y);
            float2 o1 = make_float2(d[i][j][2] + wb.x, d[i][j][3] + wb.y);
            *(float2*)&g_xw[r * H_ + col]       = o0;
            *(float2*)&g_xw[(r + 8) * H_ + col] = o1;
        }
    }
}

// ---------------------------------------------------------------------------
// Scan: one CTA per batch, 256 threads. The proven R6/R13 loop, solo.
// ---------------------------------------------------------------------------
#define UREG 192
#define USM  (H_ - UREG)

#define SCAN_SMEM_FLOATS (USM * H_ + 2 * H_)
#define SMEM_BYTES (SCAN_SMEM_FLOATS * 4)

__global__ __launch_bounds__(256, 1)
void rnn_scan(const float* __restrict__ Ub,
              float* __restrict__ Out,     // [B,S,H]
              float* __restrict__ Tfin) {  // [B,H]
    extern __shared__ float sm[];
    float2* u2  = (float2*)sm;
    float*  vsm = sm + (size_t)USM * H_;

    const int tid = threadIdx.x;
    const int b   = blockIdx.x;

    float uw[UREG];
    #pragma unroll
    for (int j = 0; j < UREG; j++)
        uw[j] = g_UwT[j * H_ + tid];

    for (int r2 = 0; r2 < USM / 2; r2++) {
        float a = g_UwT[(UREG + 2 * r2 + 0) * H_ + tid];
        float c = g_UwT[(UREG + 2 * r2 + 1) * H_ + tid];
        u2[r2 * H_ + tid] = make_float2(a, c);
    }
    __syncthreads();

    const float ub = Ub[tid];
    float t = 0.0f;

    const float* xwp = g_xw + (size_t)b * S_ * H_ + tid;
    float*       op  = Out  + (size_t)b * S_ * H_ + tid;

    float xv = __ldcs(xwp);

    for (int s = 0; s < S_; s++) {
        float v = fast_tanh(xv + t);
        float* vb = vsm + (s & 1) * H_;
        vb[tid] = v;
        __syncthreads();

        if (s + 1 < S_) xv = __ldcs(xwp + (size_t)(s + 1) * H_);

        const float4* v4 = (const float4*)vb;
        float a0 = ub, a1 = 0.f, a2 = 0.f, a3 = 0.f;
        float a4 = 0.f, a5 = 0.f, a6 = 0.f, a7 = 0.f;

        float4 vA = v4[0];
        float4 vB = v4[1];

        // Register section: rows [0,192) = 48 float4 groups, pipelined
        #pragma unroll
        for (int q = 0; q < 48; q += 2) {
            float4 nA = v4[q + 2];
            float4 nB = v4[q + 3];
            const int j = 4 * q;
            a0 += uw[j + 0] * vA.x;  a1 += uw[j + 1] * vA.y;
            a2 += uw[j + 2] * vA.z;  a3 += uw[j + 3] * vA.w;
            a4 += uw[j + 4] * vB.x;  a5 += uw[j + 5] * vB.y;
            a6 += uw[j + 6] * vB.z;  a7 += uw[j + 7] * vB.w;
            vA = nA; vB = nB;
        }

        // Shared-memory section: rows [192,256) = 16 float4 groups
        const float2* up = u2 + tid;
        #pragma unroll
        for (int q = 48; q < 64; q += 2) {
            float4 nA, nB;
            if (q + 2 < 64) { nA = v4[q + 2]; nB = v4[q + 3]; }
            else            { nA = vA;        nB = vB;        }
            const int r2b = (4 * q - UREG) >> 1;
            float2 u0 = up[(r2b + 0) * H_];
            float2 u1 = up[(r2b + 1) * H_];
            float2 uu = up[(r2b + 2) * H_];
            float2 u3 = up[(r2b + 3) * H_];
            a0 += u0.x * vA.x;  a1 += u0.y * vA.y;
            a2 += u1.x * vA.z;  a3 += u1.y * vA.w;
            a4 += uu.x * vB.x;  a5 += uu.y * vB.y;
            a6 += u3.x * vB.z;  a7 += u3.y * vB.w;
            vA = nA; vB = nB;
        }

        t = ((a0 + a1) + (a2 + a3)) + ((a4 + a5) + (a6 + a7));
        __stcs(&op[(size_t)s * H_], t);
    }

    Tfin[b * H_ + tid] = t;
}

// ---------------------------------------------------------------------------
// Launcher (serial: tiny prep -> fused tensor-core GEMM -> solo scan)
// ---------------------------------------------------------------------------
extern "C" void kernel_launch(void* const* d_in, const int* in_sizes, int n_in,
                              void* d_out, int out_size) {
    const float* x  = (const float*)d_in[0];   // [B,S,E]
    const float* Ww = (const float*)d_in[1];   // [H,E]
    const float* Wb = (const float*)d_in[2];   // [H]
    const float* Uw = (const float*)d_in[3];   // [H,H]
    const float* Ub = (const float*)d_in[4];   // [H]

    float* out  = (float*)d_out;
    float* tfin = out;                          // [B,H]
    float* O    = out + (size_t)B_ * H_;        // [B,S,H]

    cudaFuncSetAttribute(rnn_scan, cudaFuncAttributeMaxDynamicSharedMemorySize,
                         SMEM_BYTES);

    prep_uwt<<<H_, H_>>>(Uw);
    prep_wsplit<<<H_, H_>>>(Ww);
    gemm_fused<<<dim3(H_ / CTN, M_TOT / CTM), 256>>>(x, Wb);
    rnn_scan<<<B_, 256, SMEM_BYTES>>>(Ub, O, tfin);
}